// round 12
// baseline (speedup 1.0000x reference)
#include <cuda_runtime.h>
#include <cuda_bf16.h>
#include <math.h>
#include <stdint.h>

// Problem constants
#define D_MODEL 1024
#define S_LEN   2048
#define BATCH   2
#define NH      16
#define DK      64
#define DFF     4096
#define MROWS   (BATCH * S_LEN)   // 4096
#define QKV_N   3072

typedef __nv_bfloat16 bf16;

// ---------------------------------------------------------------------------
// Scratch (device globals — no allocation allowed)
// ---------------------------------------------------------------------------
__device__ __align__(128) bf16  g_xn_h[(size_t)MROWS * D_MODEL];
__device__ __align__(128) bf16  g_xn_l[(size_t)MROWS * D_MODEL];
__device__ __align__(128) bf16  g_qkv_h[(size_t)MROWS * QKV_N];
__device__ __align__(128) bf16  g_qkv_l[(size_t)MROWS * QKV_N];
__device__ __align__(128) bf16  g_at_h[(size_t)MROWS * D_MODEL];
__device__ __align__(128) bf16  g_at_l[(size_t)MROWS * D_MODEL];
__device__ __align__(128) float g_h   [(size_t)MROWS * D_MODEL];
__device__ __align__(128) bf16  g_hn_h[(size_t)MROWS * D_MODEL];
__device__ __align__(128) bf16  g_hn_l[(size_t)MROWS * D_MODEL];
__device__ __align__(128) bf16  g_ff_h[(size_t)MROWS * DFF];
__device__ __align__(128) bf16  g_ff_l[(size_t)MROWS * DFF];
// transposed split weights: WT[n][k]
__device__ __align__(128) bf16  g_wqkvT_h[(size_t)QKV_N * D_MODEL];
__device__ __align__(128) bf16  g_wqkvT_l[(size_t)QKV_N * D_MODEL];
__device__ __align__(128) bf16  g_woT_h[(size_t)D_MODEL * D_MODEL];
__device__ __align__(128) bf16  g_woT_l[(size_t)D_MODEL * D_MODEL];
__device__ __align__(128) bf16  g_w1T_h[(size_t)DFF * D_MODEL];
__device__ __align__(128) bf16  g_w1T_l[(size_t)DFF * D_MODEL];
__device__ __align__(128) bf16  g_w2T_h[(size_t)D_MODEL * DFF];
__device__ __align__(128) bf16  g_w2T_l[(size_t)D_MODEL * DFF];
__device__ float g_bqkv[QKV_N];

__device__ __forceinline__ void split_bf16(float v, bf16& h, bf16& l) {
    h = __float2bfloat16(v);
    l = __float2bfloat16(v - __bfloat162float(h));
}

// Fast e^x on the FMA pipe (degree-4, rel err ~1e-4). Avoids MUFU bottleneck.
__device__ __forceinline__ float fast_exp(float x) {
    x = fmaxf(x, -87.0f);
    float t = fmaf(x, 1.442695041f, 12582912.0f);
    float i = t - 12582912.0f;
    float f = fmaf(x, 1.442695041f, -i);
    float p = fmaf(f, 0.00898934f, 0.0558263f);
    p = fmaf(f, p, 0.2401536f);
    p = fmaf(f, p, 0.693147182f);
    p = fmaf(f, p, 1.0f);
    return p * __int_as_float(((int)i + 127) << 23);
}

// ---------------------------------------------------------------------------
// Merged weight transpose + split
// ---------------------------------------------------------------------------
__global__ __launch_bounds__(256) void wconv_all_kernel(
    const float* __restrict__ Wq, const float* __restrict__ Wk,
    const float* __restrict__ Wv, const float* __restrict__ Wo,
    const float* __restrict__ W1, const float* __restrict__ W2,
    bf16* __restrict__ qkvh, bf16* __restrict__ qkvl,
    bf16* __restrict__ woh, bf16* __restrict__ wol,
    bf16* __restrict__ w1h, bf16* __restrict__ w1l,
    bf16* __restrict__ w2h, bf16* __restrict__ w2l)
{
    __shared__ float t[32][33];
    int b = blockIdx.x;
    const float* W; bf16 *Th, *Tl; int K, N;
    if (b < 4096) {
        int s = b >> 10; b &= 1023; K = 1024; N = 1024;
        if (s == 0)      { W = Wq; Th = qkvh; Tl = qkvl; }
        else if (s == 1) { W = Wk; Th = qkvh + (size_t)1024 * 1024;
                           Tl = qkvl + (size_t)1024 * 1024; }
        else if (s == 2) { W = Wv; Th = qkvh + (size_t)2048 * 1024;
                           Tl = qkvl + (size_t)2048 * 1024; }
        else             { W = Wo; Th = woh; Tl = wol; }
    } else if (b < 8192) {
        b -= 4096; W = W1; Th = w1h; Tl = w1l; K = 1024; N = 4096;
    } else {
        b -= 8192; W = W2; Th = w2h; Tl = w2l; K = 4096; N = 1024;
    }
    const int nb = N / 32;
    const int n0 = (b % nb) * 32, k0 = (b / nb) * 32;
    const int tx = threadIdx.x, ty = threadIdx.y;
    #pragma unroll
    for (int i = 0; i < 4; i++)
        t[ty + i * 8][tx] = W[(size_t)(k0 + ty + i * 8) * N + n0 + tx];
    __syncthreads();
    #pragma unroll
    for (int i = 0; i < 4; i++) {
        float v = t[tx][ty + i * 8];
        bf16 h, l; split_bf16(v, h, l);
        size_t o = (size_t)(n0 + ty + i * 8) * K + k0 + tx;
        Th[o] = h; Tl[o] = l;
    }
}

__global__ void bias_concat_kernel(const float* bq, const float* bk, const float* bv,
                                   float* out) {
    int i = blockIdx.x * 1024 + threadIdx.x;
    out[i] = (i < 1024) ? bq[i] : (i < 2048) ? bk[i - 1024] : bv[i - 2048];
}

// ---------------------------------------------------------------------------
// LayerNorm -> bf16 hi/lo split output
// ---------------------------------------------------------------------------
__device__ __forceinline__ float block_sum_256(float v, float* red) {
    __syncthreads();
    #pragma unroll
    for (int o = 16; o; o >>= 1) v += __shfl_xor_sync(0xffffffffu, v, o);
    if ((threadIdx.x & 31) == 0) red[threadIdx.x >> 5] = v;
    __syncthreads();
    if (threadIdx.x < 32) {
        float w = (threadIdx.x < 8) ? red[threadIdx.x] : 0.0f;
        #pragma unroll
        for (int o = 4; o; o >>= 1) w += __shfl_xor_sync(0xffffffffu, w, o);
        if (threadIdx.x == 0) red[0] = w;
    }
    __syncthreads();
    return red[0];
}

__global__ __launch_bounds__(256) void ln_split_kernel(
    const float* __restrict__ x, const float* __restrict__ g,
    const float* __restrict__ b, bf16* __restrict__ oh, bf16* __restrict__ ol)
{
    __shared__ float red[32];
    const int row = blockIdx.x;
    const int t = threadIdx.x;
    float4 v = reinterpret_cast<const float4*>(x + (size_t)row * D_MODEL)[t];

    float s = v.x + v.y + v.z + v.w;
    float mu = block_sum_256(s, red) * (1.0f / (float)D_MODEL);

    float dx = v.x - mu, dy = v.y - mu, dz = v.z - mu, dw = v.w - mu;
    float sq = dx * dx + dy * dy + dz * dz + dw * dw;
    float var = block_sum_256(sq, red) * (1.0f / (float)D_MODEL);
    float inv = rsqrtf(var + 1e-5f);

    float4 gg = reinterpret_cast<const float4*>(g)[t];
    float4 bb = reinterpret_cast<const float4*>(b)[t];
    float o0 = dx * inv * gg.x + bb.x;
    float o1 = dy * inv * gg.y + bb.y;
    float o2 = dz * inv * gg.z + bb.z;
    float o3 = dw * inv * gg.w + bb.w;

    bf16 h0, l0, h1, l1, h2, l2, h3, l3;
    split_bf16(o0, h0, l0); split_bf16(o1, h1, l1);
    split_bf16(o2, h2, l2); split_bf16(o3, h3, l3);
    size_t off = (size_t)row * D_MODEL + t * 4;
    __nv_bfloat162* ph = reinterpret_cast<__nv_bfloat162*>(oh + off);
    ph[0] = __halves2bfloat162(h0, h1);
    ph[1] = __halves2bfloat162(h2, h3);
    __nv_bfloat162* pl = reinterpret_cast<__nv_bfloat162*>(ol + off);
    pl[0] = __halves2bfloat162(l0, l1);
    pl[1] = __halves2bfloat162(l2, l3);
}

// ---------------------------------------------------------------------------
// Shared GEMM building blocks (SW128 swizzle, ldmatrix, mma)
// ---------------------------------------------------------------------------
__device__ __forceinline__ uint32_t swz_addr(uint32_t base, int r, int b) {
    return base + r * 128 + ((((b >> 4) ^ (r & 7)) & 7) << 4) + (b & 15);
}

// A-fragment 16x16 at (rows R..R+15, bytes cb..cb+31) via one ldmatrix.x4.
// d order: (R,cb),(R+8,cb),(R,cb+16),(R+8,cb+16).
__device__ __forceinline__ void ldsm_a(uint32_t d[4], uint32_t base, int lane,
                                       int R, int cb) {
    const int row = R + (lane & 7) + (((lane >> 3) & 1) << 3);
    const int byt = cb + ((lane >> 4) << 4);
    const uint32_t addr = swz_addr(base, row, byt);
    asm volatile("ldmatrix.sync.aligned.m8n8.x4.shared.b16 {%0,%1,%2,%3}, [%4];"
                 : "=r"(d[0]), "=r"(d[1]), "=r"(d[2]), "=r"(d[3]) : "r"(addr));
}

// B-fragments for two adjacent n8 tiles:
// d0=(N0,cb) d1=(N0,cb+16) d2=(N0+8,cb) d3=(N0+8,cb+16)
__device__ __forceinline__ void ldsm_b2(uint32_t d[4], uint32_t base, int lane,
                                        int N0, int cb) {
    const int row = N0 + (lane & 7) + ((lane >> 4) << 3);
    const int byt = cb + (((lane >> 3) & 1) << 4);
    const uint32_t addr = swz_addr(base, row, byt);
    asm volatile("ldmatrix.sync.aligned.m8n8.x4.shared.b16 {%0,%1,%2,%3}, [%4];"
                 : "=r"(d[0]), "=r"(d[1]), "=r"(d[2]), "=r"(d[3]) : "r"(addr));
}

__device__ __forceinline__ void mma_bf16(float c[4], const uint32_t a[4],
                                         const uint32_t b[2]) {
    asm volatile(
        "mma.sync.aligned.m16n8k16.row.col.f32.bf16.bf16.f32 "
        "{%0,%1,%2,%3}, {%4,%5,%6,%7}, {%8,%9}, {%0,%1,%2,%3};"
        : "+f"(c[0]), "+f"(c[1]), "+f"(c[2]), "+f"(c[3])
        : "r"(a[0]), "r"(a[1]), "r"(a[2]), "r"(a[3]), "r"(b[0]), "r"(b[1]));
}

// ---------------------------------------------------------------------------
// bf16 split-precision tensor-core GEMM.
// Mainloop schedule (R12): after the stage barrier, issue ALL pass-1/2
// fragment LDSMs first, THEN the next-stage cp.async burst (so fragment loads
// don't queue behind 16 cp.async on the LSU), then MMA pass1; fBl LDSMs are
// issued between pass1 and pass2 so pass3 never waits.
// ---------------------------------------------------------------------------
#define BK 32
#define STAGE_BYTES 32768
#define A_HALF_BYTES 16384
#define STAGES 3
#define GEMM_SMEM_BYTES (STAGES * STAGE_BYTES)   // 98304

__global__ __launch_bounds__(256, 2) void gemm_bf16_kernel(
    const bf16* __restrict__ Ah, const bf16* __restrict__ Al,
    const bf16* __restrict__ Bh, const bf16* __restrict__ Bl,
    const float* __restrict__ bias, const float* __restrict__ resid,
    float* __restrict__ Cf, bf16* __restrict__ Ch, bf16* __restrict__ Cl,
    int M, int N, int K, int relu)
{
    extern __shared__ char smc[];
    const int tid = threadIdx.x;
    const int lane = tid & 31;
    const int w = tid >> 5;
    const int wm = w & 1, wn = w >> 1;
    const int g = lane >> 2, tg = lane & 3;
    const int bx = blockIdx.x, by = blockIdx.y;

    const bf16* Asrc[2] = {Ah + (size_t)(by * 128) * K, Al + (size_t)(by * 128) * K};
    const bf16* Bsrc[2] = {Bh + (size_t)(bx * 128) * K, Bl + (size_t)(bx * 128) * K};

    uint32_t smem_base = (uint32_t)__cvta_generic_to_shared(smc);

    float acc[4][4][4];
    #pragma unroll
    for (int mi = 0; mi < 4; mi++)
        #pragma unroll
        for (int ni = 0; ni < 4; ni++)
            #pragma unroll
            for (int c = 0; c < 4; c++) acc[mi][ni][c] = 0.0f;

    const int nk = K / BK;

#define LOAD_STAGE(s, k0)                                                     \
    do {                                                                      \
        uint32_t sb = smem_base + (s) * STAGE_BYTES;                          \
        _Pragma("unroll")                                                     \
        for (int i = 0; i < 4; i++) {                                         \
            int f = i * 256 + tid;                                            \
            int row = f >> 3, c = f & 7;                                      \
            uint32_t sw = ((uint32_t)((c ^ (row & 7)) & 7)) << 4;             \
            uint32_t dA = sb + row * 128 + sw;                                \
            uint32_t dB = dA + A_HALF_BYTES;                                  \
            const bf16* sA = Asrc[c >> 2] + (size_t)row * K + (k0) + (c & 3) * 8; \
            const bf16* sB = Bsrc[c >> 2] + (size_t)row * K + (k0) + (c & 3) * 8; \
            asm volatile("cp.async.cg.shared.global [%0], [%1], 16;" ::       \
                         "r"(dA), "l"(sA));                                   \
            asm volatile("cp.async.cg.shared.global [%0], [%1], 16;" ::       \
                         "r"(dB), "l"(sB));                                   \
        }                                                                     \
        asm volatile("cp.async.commit_group;");                               \
    } while (0)

    LOAD_STAGE(0, 0);
    LOAD_STAGE(1, BK);

    for (int kt = 0; kt < nk; kt++) {
        asm volatile("cp.async.wait_group 1;" ::: "memory");
        __syncthreads();

        const uint32_t sAu = smem_base + (kt % STAGES) * STAGE_BYTES;
        const uint32_t sBu = sAu + A_HALF_BYTES;

        #pragma unroll
        for (int kf = 0; kf < 2; kf++) {
            const int cb = kf * 32;
            uint32_t fAh[4][4], fBh[4][2], fAl[4][4], fBl[4][2];

            // --- fragment loads for passes 1 & 2 issued FIRST ---
            #pragma unroll
            for (int mi = 0; mi < 4; mi++)
                ldsm_a(fAh[mi], sAu, lane, wm * 64 + mi * 16, cb);
            #pragma unroll
            for (int np = 0; np < 2; np++) {
                uint32_t t4[4];
                ldsm_b2(t4, sBu, lane, wn * 32 + np * 16, cb);
                fBh[np * 2][0] = t4[0]; fBh[np * 2][1] = t4[1];
                fBh[np * 2 + 1][0] = t4[2]; fBh[np * 2 + 1][1] = t4[3];
            }
            #pragma unroll
            for (int mi = 0; mi < 4; mi++)
                ldsm_a(fAl[mi], sAu, lane, wm * 64 + mi * 16, cb + 64);

            // --- next-stage cp.async AFTER fragment loads (kf==0 only) ---
            if (kf == 0) {
                if (kt + 2 < nk) {
                    LOAD_STAGE((kt + 2) % STAGES, (kt + 2) * BK);
                } else {
                    asm volatile("cp.async.commit_group;");
                }
            }

            // pass 1: Ah * Bh
            #pragma unroll
            for (int mi = 0; mi < 4; mi++)
                #pragma unroll
                for (int ni = 0; ni < 4; ni++)
                    mma_bf16(acc[mi][ni], fAh[mi], fBh[ni]);

            // fBl loads overlap with pass-2 MMAs
            #pragma unroll
            for (int np = 0; np < 2; np++) {
                uint32_t t4[4];
                ldsm_b2(t4, sBu, lane, wn * 32 + np * 16, cb + 64);
                fBl[np * 2][0] = t4[0]; fBl[np * 2][1] = t4[1];
                fBl[np * 2 + 1][0] = t4[2]; fBl[np * 2 + 1][1] = t4[3];
            }

            // pass 2: Al * Bh
            #pragma unroll
            for (int mi = 0; mi < 4; mi++)
                #pragma unroll
                for (int ni = 0; ni < 4; ni++)
                    mma_bf16(acc[mi][ni], fAl[mi], fBh[ni]);

            // pass 3: Ah * Bl
            #pragma unroll
            for (int mi = 0; mi < 4; mi++)
                #pragma unroll
                for (int ni = 0; ni < 4; ni++)
                    mma_bf16(acc[mi][ni], fAh[mi], fBl[ni]);
        }
    }

    const int bm = by * 128 + wm * 64;
    const int bn = bx * 128 + wn * 32;
    #pragma unroll
    for (int mi = 0; mi < 4; mi++) {
        #pragma unroll
        for (int ni = 0; ni < 4; ni++) {
            const int c0 = bn + ni * 8 + tg * 2;
            const float b0 = bias[c0], b1 = bias[c0 + 1];
            #pragma unroll
            for (int half = 0; half < 2; half++) {
                const int r = bm + mi * 16 + g + half * 8;
                float v0 = acc[mi][ni][half * 2 + 0] + b0;
                float v1 = acc[mi][ni][half * 2 + 1] + b1;
                if (resid) {
                    const float2 rr = *reinterpret_cast<const float2*>(
                        resid + (size_t)r * N + c0);
                    v0 += rr.x; v1 += rr.y;
                }
                if (relu) { v0 = fmaxf(v0, 0.0f); v1 = fmaxf(v1, 0.0f); }
                if (Cf) {
                    float2 o; o.x = v0; o.y = v1;
                    *reinterpret_cast<float2*>(Cf + (size_t)r * N + c0) = o;
                }
                if (Ch) {
                    bf16 h0, l0, h1, l1;
                    split_bf16(v0, h0, l0); split_bf16(v1, h1, l1);
                    *reinterpret_cast<__nv_bfloat162*>(Ch + (size_t)r * N + c0) =
                        __halves2bfloat162(h0, h1);
                    *reinterpret_cast<__nv_bfloat162*>(Cl + (size_t)r * N + c0) =
                        __halves2bfloat162(l0, l1);
                }
            }
        }
    }
}

// ---------------------------------------------------------------------------
// Causal flash attention via mma.sync bf16 hi/lo (ldmatrix fragment loads).
// ---------------------------------------------------------------------------
#define AT_Q_OFF   0        // 2 chunks x 16KB = 32KB
#define AT_K_OFF   32768    // 2 chunks x 16KB
#define AT_VT_OFF  65536    // 4 chunks x 8KB (64 rows x 128B)
#define AT_P_OFF   98304    // 4 chunks x 16KB
#define AT_RED_OFF 163840
#define ATTN_SMEM_BYTES (AT_RED_OFF + 1536 * 4)   // 169984

#define SWZ(r, b) (((((b) >> 4) ^ ((r) & 7)) & 7) << 4 | ((b) & 15))

__global__ __launch_bounds__(256, 1) void attn_mma_kernel(
    const bf16* __restrict__ QKVh, const bf16* __restrict__ QKVl,
    bf16* __restrict__ Oh, bf16* __restrict__ Ol)
{
    extern __shared__ char smc[];
    float* red  = reinterpret_cast<float*>(smc + AT_RED_OFF);
    float* m_s  = red;
    float* l_s  = red + 128;
    float* sc_s = red + 256;
    float* nm_s = red + 384;
    float* pmax = red + 512;    // [4][128]
    float* psum = red + 1024;   // [4][128]

    const int qt = blockIdx.x, hh = blockIdx.y, bb = blockIdx.z;
    const int tid = threadIdx.x;
    const int lane = tid & 31;
    const int w = tid >> 5;
    const int g = lane >> 2, tg = lane & 3;
    const int wm = w & 1, wn = w >> 1;     // QK mapping
    const int wq = w & 3, wc = w >> 2;     // PV mapping
    const int qbase = qt * 128;
    const int grow0 = bb * S_LEN + qbase;
    uint32_t smem_base = (uint32_t)__cvta_generic_to_shared(smc);

#define AT_LOAD_TILE(dstoff, rbase, colbase)                                  \
    do {                                                                      \
        _Pragma("unroll")                                                     \
        for (int i = 0; i < 4; i++) {                                         \
            int f = i * 256 + tid;                                            \
            int row = f >> 3, c = f & 7;                                      \
            uint32_t dst = smem_base + (dstoff) + row * 128 +                 \
                           (((uint32_t)((c ^ (row & 7)) & 7)) << 4);          \
            const bf16* src = ((c < 4) ? QKVh : QKVl) +                       \
                (size_t)((rbase) + row) * QKV_N + (colbase) + (c & 3) * 8;    \
            asm volatile("cp.async.cg.shared.global [%0], [%1], 16;" ::       \
                         "r"(dst), "l"(src));                                 \
        }                                                                     \
    } while (0)

    // Q tiles (2 chunks)
    AT_LOAD_TILE(AT_Q_OFF, grow0, hh * 64);
    AT_LOAD_TILE(AT_Q_OFF + 16384, grow0, hh * 64 + 32);
    asm volatile("cp.async.commit_group;");

    if (tid < 128) { m_s[tid] = -INFINITY; l_s[tid] = 0.0f; }

    float o[2][4][4];
    #pragma unroll
    for (int mi = 0; mi < 2; mi++)
        #pragma unroll
        for (int ni = 0; ni < 4; ni++)
            #pragma unroll
            for (int c = 0; c < 4; c++) o[mi][ni][c] = 0.0f;

    for (int kt = 0; kt <= qt; kt++) {
        const int kbase = kt * 128;
        const int krow0 = bb * S_LEN + kbase;

        AT_LOAD_TILE(AT_K_OFF, krow0, 1024 + hh * 64);
        AT_LOAD_TILE(AT_K_OFF + 16384, krow0, 1024 + hh * 64 + 32);
        asm volatile("cp.async.commit_group;");

        // V transpose: V[j][c] -> Vt[c][j] hi/lo (B-layout, 4 j-chunks)
        {
            const int cg = (tid & 15) * 4;
            const int j0 = tid >> 4;
            #pragma unroll
            for (int jj = 0; jj < 8; jj++) {
                const int j = j0 + jj * 16;
                const size_t goff = (size_t)(krow0 + j) * QKV_N + 2048 +
                                    hh * 64 + cg;
                unsigned long long vh =
                    *reinterpret_cast<const unsigned long long*>(QKVh + goff);
                unsigned long long vl =
                    *reinterpret_cast<const unsigned long long*>(QKVl + goff);
                const int cbase = AT_VT_OFF + (j >> 5) * 8192;
                const int bh = (j & 31) * 2;
                #pragma unroll
                for (int u = 0; u < 4; u++) {
                    const int c = cg + u;
                    unsigned short eh = (unsigned short)(vh >> (16 * u));
                    unsigned short el = (unsigned short)(vl >> (16 * u));
                    *reinterpret_cast<unsigned short*>(
                        smc + cbase + c * 128 + SWZ(c, bh)) = eh;
                    *reinterpret_cast<unsigned short*>(
                        smc + cbase + c * 128 + SWZ(c, bh + 64)) = el;
                }
            }
        }

        asm volatile("cp.async.wait_group 0;" ::: "memory");
        __syncthreads();   // (1)

        // ---- QK^T ----
        float acc[4][4][4];
        #pragma unroll
        for (int mi = 0; mi < 4; mi++)
            #pragma unroll
            for (int ni = 0; ni < 4; ni++)
                #pragma unroll
                for (int c = 0; c < 4; c++) acc[mi][ni][c] = 0.0f;

        #pragma unroll
        for (int ck = 0; ck < 2; ck++) {
            const uint32_t sQ = smem_base + AT_Q_OFF + ck * 16384;
            const uint32_t sK = smem_base + AT_K_OFF + ck * 16384;
            #pragma unroll
            for (int kf = 0; kf < 2; kf++) {
                const int cb = kf * 32;
                uint32_t fAh[4][4], fBh[4][2], fAl[4][4], fBl[4][2];
                #pragma unroll
                for (int mi = 0; mi < 4; mi++)
                    ldsm_a(fAh[mi], sQ, lane, wm * 64 + mi * 16, cb);
                #pragma unroll
                for (int np = 0; np < 2; np++) {
                    uint32_t t4[4];
                    ldsm_b2(t4, sK, lane, wn * 32 + np * 16, cb);
                    fBh[np * 2][0] = t4[0]; fBh[np * 2][1] = t4[1];
                    fBh[np * 2 + 1][0] = t4[2]; fBh[np * 2 + 1][1] = t4[3];
                }
                #pragma unroll
                for (int mi = 0; mi < 4; mi++)
                    ldsm_a(fAl[mi], sQ, lane, wm * 64 + mi * 16, cb + 64);
                #pragma unroll
                for (int mi = 0; mi < 4; mi++)
                    #pragma unroll
                    for (int ni = 0; ni < 4; ni++)
                        mma_bf16(acc[mi][ni], fAh[mi], fBh[ni]);
                #pragma unroll
                for (int np = 0; np < 2; np++) {
                    uint32_t t4[4];
                    ldsm_b2(t4, sK, lane, wn * 32 + np * 16, cb + 64);
                    fBl[np * 2][0] = t4[0]; fBl[np * 2][1] = t4[1];
                    fBl[np * 2 + 1][0] = t4[2]; fBl[np * 2 + 1][1] = t4[3];
                }
                #pragma unroll
                for (int mi = 0; mi < 4; mi++)
                    #pragma unroll
                    for (int ni = 0; ni < 4; ni++)
                        mma_bf16(acc[mi][ni], fAl[mi], fBh[ni]);
                #pragma unroll
                for (int mi = 0; mi < 4; mi++)
                    #pragma unroll
                    for (int ni = 0; ni < 4; ni++)
                        mma_bf16(acc[mi][ni], fAh[mi], fBl[ni]);
            }
        }

        // ---- scale + causal mask ----
        #pragma unroll
        for (int mi = 0; mi < 4; mi++) {
            const int qi0 = qbase + wm * 64 + mi * 16 + g;
            #pragma unroll
            for (int ni = 0; ni < 4; ni++) {
                const int kj = kbase + wn * 32 + ni * 8 + tg * 2;
                acc[mi][ni][0] = (kj     <= qi0) ? acc[mi][ni][0] * 0.125f : -1e30f;
                acc[mi][ni][1] = (kj + 1 <= qi0) ? acc[mi][ni][1] * 0.125f : -1e30f;
                acc[mi][ni][2] = (kj     <= qi0 + 8) ? acc[mi][ni][2] * 0.125f : -1e30f;
                acc[mi][ni][3] = (kj + 1 <= qi0 + 8) ? acc[mi][ni][3] * 0.125f : -1e30f;
            }
        }

        // ---- row max ----
        #pragma unroll
        for (int mi = 0; mi < 4; mi++) {
            float m0 = -INFINITY, m1 = -INFINITY;
            #pragma unroll
            for (int ni = 0; ni < 4; ni++) {
                m0 = fmaxf(m0, fmaxf(acc[mi][ni][0], acc[mi][ni][1]));
                m1 = fmaxf(m1, fmaxf(acc[mi][ni][2], acc[mi][ni][3]));
            }
            m0 = fmaxf(m0, __shfl_xor_sync(0xffffffffu, m0, 1));
            m0 = fmaxf(m0, __shfl_xor_sync(0xffffffffu, m0, 2));
            m1 = fmaxf(m1, __shfl_xor_sync(0xffffffffu, m1, 1));
            m1 = fmaxf(m1, __shfl_xor_sync(0xffffffffu, m1, 2));
            if (tg == 0) {
                const int r = wm * 64 + mi * 16 + g;
                pmax[wn * 128 + r] = m0;
                pmax[wn * 128 + r + 8] = m1;
            }
        }
        __syncthreads();   // (2)
        if (tid < 128) {
            float nm = m_s[tid];
            #pragma unroll
            for (int wi = 0; wi < 4; wi++) nm = fmaxf(nm, pmax[wi * 128 + tid]);
            sc_s[tid] = fast_exp(m_s[tid] - nm);
            nm_s[tid] = nm;
            m_s[tid] = nm;
        }
        __syncthreads();   // (3)

        // ---- exp, P split + store, row sums ----
        #pragma unroll
        for (int mi = 0; mi < 4; mi++) {
            const int r0 = wm * 64 + mi * 16 + g;
            const int r1 = r0 + 8;
            const float nm0 = nm_s[r0], nm1 = nm_s[r1];
            float s0 = 0.0f, s1 = 0.0f;
            const int pb0 = AT_P_OFF + wn * 16384 + r0 * 128;
            const int pb1 = AT_P_OFF + wn * 16384 + r1 * 128;
            #pragma unroll
            for (int ni = 0; ni < 4; ni++) {
                float p00 = fast_exp(acc[mi][ni][0] - nm0);
                float p01 = fast_exp(acc[mi][ni][1] - nm0);
                float p10 = fast_exp(acc[mi][ni][2] - nm1);
                float p11 = fast_exp(acc[mi][ni][3] - nm1);
                s0 += p00 + p01;
                s1 += p10 + p11;
                const int bh = ni * 16 + tg * 4;
                bf16 h0, l0, h1, l1;
                split_bf16(p00, h0, l0); split_bf16(p01, h1, l1);
                *reinterpret_cast<__nv_bfloat162*>(smc + pb0 + SWZ(r0, bh)) =
                    __halves2bfloat162(h0, h1);
                *reinterpret_cast<__nv_bfloat162*>(smc + pb0 + SWZ(r0, bh + 64)) =
                    __halves2bfloat162(l0, l1);
                split_bf16(p10, h0, l0); split_bf16(p11, h1, l1);
                *reinterpret_cast<__nv_bfloat162*>(smc + pb1 + SWZ(r1, bh)) =
                    __halves2bfloat162(h0, h1);
                *reinterpret_cast<__nv_bfloat162*>(smc + pb1 + SWZ(r1, bh + 64)) =
                    __halves2bfloat162(l0, l1);
            }
            s0 += __shfl_xor_sync(0xffffffffu, s0, 1);
            s0 += __shfl_xor_sync(0xffffffffu, s0, 2);
            s1 += __shfl_xor_sync(0xffffffffu, s1, 1);
            s1 += __shfl_xor_sync(0xffffffffu, s1, 2);
            if (tg == 0) {
                psum[wn * 128 + r0] = s0;
                psum[wn * 128 + r1] = s1;
            }
        }
        __syncthreads();   // (4)
        if (tid < 128) {
            l_s[tid] = l_s[tid] * sc_s[tid] +
                psum[tid] + psum[128 + tid] + psum[256 + tid] + psum[384 + tid];
        }

        // ---- rescale O, then PV ----
        #pragma unroll
        for (int mi = 0; mi < 2; mi++) {
            const int r0 = wq * 32 + mi * 16 + g;
            const float sc0 = sc_s[r0], sc1 = sc_s[r0 + 8];
            #pragma unroll
            for (int ni = 0; ni < 4; ni++) {
                o[mi][ni][0] *= sc0; o[mi][ni][1] *= sc0;
                o[mi][ni][2] *= sc1; o[mi][ni][3] *= sc1;
            }
        }
        #pragma unroll
        for (int cj = 0; cj < 4; cj++) {
            const uint32_t sP = smem_base + AT_P_OFF + cj * 16384;
            const uint32_t sV = smem_base + AT_VT_OFF + cj * 8192;
            #pragma unroll
            for (int kf = 0; kf < 2; kf++) {
                const int cb = kf * 32;
                uint32_t fPh[2][4], fVh[4][2], fPl[2][4], fVl[4][2];
                #pragma unroll
                for (int mi = 0; mi < 2; mi++)
                    ldsm_a(fPh[mi], sP, lane, wq * 32 + mi * 16, cb);
                #pragma unroll
                for (int np = 0; np < 2; np++) {
                    uint32_t t4[4];
                    ldsm_b2(t4, sV, lane, wc * 32 + np * 16, cb);
                    fVh[np * 2][0] = t4[0]; fVh[np * 2][1] = t4[1];
                    fVh[np * 2 + 1][0] = t4[2]; fVh[np * 2 + 1][1] = t4[3];
                }
                #pragma unroll
                for (int mi = 0; mi < 2; mi++)
                    ldsm_a(fPl[mi], sP, lane, wq * 32 + mi * 16, cb + 64);
                #pragma unroll
                for (int mi = 0; mi < 2; mi++)
                    #pragma unroll
                    for (int ni = 0; ni < 4; ni++)
                        mma_bf16(o[mi][ni], fPh[mi], fVh[ni]);
                #pragma unroll
                for (int np = 0; np < 2; np++) {
                    uint32_t t4[4];
                    ldsm_b2(t4, sV, lane, wc * 32 + np * 16, cb + 64);
                    fVl[np * 2][0] = t4[0]; fVl[np * 2][1] = t4[1];
                    fVl[np * 2 + 1][0] = t4[2]; fVl[np * 2 + 1][1] = t4[3];
                }
                #pragma unroll
                for (int mi = 0; mi < 2; mi++)
                    #pragma unroll
                    for (int ni = 0; ni < 4; ni++)
                        mma_bf16(o[mi][ni], fPl[mi], fVh[ni]);
                #pragma unroll
                for (int mi = 0; mi < 2; mi++)
                    #pragma unroll
                    for (int ni = 0; ni < 4; ni++)
                        mma_bf16(o[mi][ni], fPh[mi], fVl[ni]);
            }
        }
        __syncthreads();   // (5)
    }

    // ---- output ----
    #pragma unroll
    for (int mi = 0; mi < 2; mi++) {
        #pragma unroll
        for (int half = 0; half < 2; half++) {
            const int r = wq * 32 + mi * 16 + g + half * 8;
            const float inv = 1.0f / l_s[r];
            const size_t grow = (size_t)(grow0 + r) * D_MODEL +
                                hh * 64 + wc * 32 + tg * 2;
            #pragma unroll
            for (int ni = 0; ni < 4; ni++) {
                float v0 = o[mi][ni][half * 2 + 0] * inv;
                float v1 = o[mi][ni][half * 2 + 1] * inv;
                bf16 h0, l0, h1, l1;
                split_bf16(v0, h0, l0); split_bf16(v1, h1, l1);
                *reinterpret_cast<__nv_bfloat162*>(Oh + grow + ni * 8) =
                    __halves2bfloat162(h0, h1);
                *reinterpret_cast<__nv_bfloat162*>(Ol + grow + ni * 8) =
                    __halves2bfloat162(l0, l1);
            }
        }
    }
}

// ---------------------------------------------------------------------------
// kernel_launch
// ---------------------------------------------------------------------------
extern "C" void kernel_launch(void* const* d_in, const int* in_sizes, int n_in,
                              void* d_out, int out_size)
{
    const float* x   = (const float*)d_in[0];
    const float* Wq  = (const float*)d_in[2];
    const float* bq  = (const float*)d_in[3];
    const float* Wk  = (const float*)d_in[4];
    const float* bk  = (const float*)d_in[5];
    const float* Wv  = (const float*)d_in[6];
    const float* bv  = (const float*)d_in[7];
    const float* Wo  = (const float*)d_in[8];
    const float* bo  = (const float*)d_in[9];
    const float* W1  = (const float*)d_in[10];
    const float* b1  = (const float*)d_in[11];
    const float* W2  = (const float*)d_in[12];
    const float* b2  = (const float*)d_in[13];
    const float* g1  = (const float*)d_in[14];
    const float* be1 = (const float*)d_in[15];
    const float* g2  = (const float*)d_in[16];
    const float* be2 = (const float*)d_in[17];
    float* out = (float*)d_out;

    bf16 *xnh, *xnl, *qkvh, *qkvl, *ath, *atl, *hnh, *hnl, *ffh, *ffl;
    bf16 *wqkvh, *wqkvl, *woh, *wol, *w1h, *w1l, *w2h, *w2l;
    float *h, *bqkv;
    cudaGetSymbolAddress((void**)&xnh, g_xn_h);
    cudaGetSymbolAddress((void**)&xnl, g_xn_l);
    cudaGetSymbolAddress((void**)&qkvh, g_qkv_h);
    cudaGetSymbolAddress((void**)&qkvl, g_qkv_l);
    cudaGetSymbolAddress((void**)&ath, g_at_h);
    cudaGetSymbolAddress((void**)&atl, g_at_l);
    cudaGetSymbolAddress((void**)&h,   g_h);
    cudaGetSymbolAddress((void**)&hnh, g_hn_h);
    cudaGetSymbolAddress((void**)&hnl, g_hn_l);
    cudaGetSymbolAddress((void**)&ffh, g_ff_h);
    cudaGetSymbolAddress((void**)&ffl, g_ff_l);
    cudaGetSymbolAddress((void**)&wqkvh, g_wqkvT_h);
    cudaGetSymbolAddress((void**)&wqkvl, g_wqkvT_l);
    cudaGetSymbolAddress((void**)&woh, g_woT_h);
    cudaGetSymbolAddress((void**)&wol, g_woT_l);
    cudaGetSymbolAddress((void**)&w1h, g_w1T_h);
    cudaGetSymbolAddress((void**)&w1l, g_w1T_l);
    cudaGetSymbolAddress((void**)&w2h, g_w2T_h);
    cudaGetSymbolAddress((void**)&w2l, g_w2T_l);
    cudaGetSymbolAddress((void**)&bqkv, g_bqkv);

    cudaFuncSetAttribute(attn_mma_kernel, cudaFuncAttributeMaxDynamicSharedMemorySize,
                         ATTN_SMEM_BYTES);
    cudaFuncSetAttribute(gemm_bf16_kernel, cudaFuncAttributeMaxDynamicSharedMemorySize,
                         GEMM_SMEM_BYTES);

    const dim3 blk(256);
    const dim3 wblk(32, 8);

    // 1
    wconv_all_kernel<<<12288, wblk>>>(Wq, Wk, Wv, Wo, W1, W2,
                                      wqkvh, wqkvl, woh, wol,
                                      w1h, w1l, w2h, w2l);
    // 2
    bias_concat_kernel<<<3, 1024>>>(bq, bk, bv, bqkv);
    // 3
    ln_split_kernel<<<MROWS, blk>>>(x, g1, be1, xnh, xnl);
    // 4: QKV projection -> bf16 hi/lo
    gemm_bf16_kernel<<<dim3(QKV_N / 128, MROWS / 128), blk, GEMM_SMEM_BYTES>>>(
        xnh, xnl, wqkvh, wqkvl, bqkv, nullptr, nullptr, qkvh, qkvl,
        MROWS, QKV_N, D_MODEL, 0);
    // 5: tensor-core attention
    attn_mma_kernel<<<dim3(S_LEN / 128, NH, BATCH), blk, ATTN_SMEM_BYTES>>>(
        qkvh, qkvl, ath, atl);
    // 6 (profiled)
    gemm_bf16_kernel<<<dim3(D_MODEL / 128, MROWS / 128), blk, GEMM_SMEM_BYTES>>>(
        ath, atl, woh, wol, bo, x, h, nullptr, nullptr,
        MROWS, D_MODEL, D_MODEL, 0);
    // 7
    ln_split_kernel<<<MROWS, blk>>>(h, g2, be2, hnh, hnl);
    // 8
    gemm_bf16_kernel<<<dim3(DFF / 128, MROWS / 128), blk, GEMM_SMEM_BYTES>>>(
        hnh, hnl, w1h, w1l, b1, nullptr, nullptr, ffh, ffl,
        MROWS, DFF, D_MODEL, 1);
    // 9
    gemm_bf16_kernel<<<dim3(D_MODEL / 128, MROWS / 128), blk, GEMM_SMEM_BYTES>>>(
        ffh, ffl, w2h, w2l, b2, h, out, nullptr, nullptr,
        MROWS, D_MODEL, DFF, 0);
}

// round 16
// speedup vs baseline: 1.0076x; 1.0076x over previous
#include <cuda_runtime.h>
#include <cuda_bf16.h>
#include <math.h>
#include <stdint.h>

// Problem constants
#define D_MODEL 1024
#define S_LEN   2048
#define BATCH   2
#define NH      16
#define DK      64
#define DFF     4096
#define MROWS   (BATCH * S_LEN)   // 4096
#define QKV_N   3072

typedef __nv_bfloat16 bf16;

// ---------------------------------------------------------------------------
// Scratch (device globals — no allocation allowed)
// ---------------------------------------------------------------------------
__device__ __align__(128) bf16  g_xn_h[(size_t)MROWS * D_MODEL];
__device__ __align__(128) bf16  g_xn_l[(size_t)MROWS * D_MODEL];
__device__ __align__(128) bf16  g_qkv_h[(size_t)MROWS * QKV_N];
__device__ __align__(128) bf16  g_qkv_l[(size_t)MROWS * QKV_N];
__device__ __align__(128) bf16  g_at_h[(size_t)MROWS * D_MODEL];
__device__ __align__(128) bf16  g_at_l[(size_t)MROWS * D_MODEL];
__device__ __align__(128) float g_h   [(size_t)MROWS * D_MODEL];
__device__ __align__(128) bf16  g_hn_h[(size_t)MROWS * D_MODEL];
__device__ __align__(128) bf16  g_hn_l[(size_t)MROWS * D_MODEL];
__device__ __align__(128) bf16  g_ff_h[(size_t)MROWS * DFF];
__device__ __align__(128) bf16  g_ff_l[(size_t)MROWS * DFF];
// transposed split weights: WT[n][k]
__device__ __align__(128) bf16  g_wqkvT_h[(size_t)QKV_N * D_MODEL];
__device__ __align__(128) bf16  g_wqkvT_l[(size_t)QKV_N * D_MODEL];
__device__ __align__(128) bf16  g_woT_h[(size_t)D_MODEL * D_MODEL];
__device__ __align__(128) bf16  g_woT_l[(size_t)D_MODEL * D_MODEL];
__device__ __align__(128) bf16  g_w1T_h[(size_t)DFF * D_MODEL];
__device__ __align__(128) bf16  g_w1T_l[(size_t)DFF * D_MODEL];
__device__ __align__(128) bf16  g_w2T_h[(size_t)D_MODEL * DFF];
__device__ __align__(128) bf16  g_w2T_l[(size_t)D_MODEL * DFF];
__device__ float g_bqkv[QKV_N];

__device__ __forceinline__ void split_bf16(float v, bf16& h, bf16& l) {
    h = __float2bfloat16(v);
    l = __float2bfloat16(v - __bfloat162float(h));
}

// pack two bf16 into uint32 (lo in low 16 bits — matches __halves2bfloat162)
__device__ __forceinline__ uint32_t pack2(bf16 lo, bf16 hi) {
    return (uint32_t)__bfloat16_as_ushort(lo) |
           ((uint32_t)__bfloat16_as_ushort(hi) << 16);
}

// Fast e^x on the FMA pipe (degree-4, rel err ~1e-4). Avoids MUFU bottleneck.
__device__ __forceinline__ float fast_exp(float x) {
    x = fmaxf(x, -87.0f);
    float t = fmaf(x, 1.442695041f, 12582912.0f);
    float i = t - 12582912.0f;
    float f = fmaf(x, 1.442695041f, -i);
    float p = fmaf(f, 0.00898934f, 0.0558263f);
    p = fmaf(f, p, 0.2401536f);
    p = fmaf(f, p, 0.693147182f);
    p = fmaf(f, p, 1.0f);
    return p * __int_as_float(((int)i + 127) << 23);
}

// ---------------------------------------------------------------------------
// Merged weight transpose + split
// ---------------------------------------------------------------------------
__global__ __launch_bounds__(256) void wconv_all_kernel(
    const float* __restrict__ Wq, const float* __restrict__ Wk,
    const float* __restrict__ Wv, const float* __restrict__ Wo,
    const float* __restrict__ W1, const float* __restrict__ W2,
    bf16* __restrict__ qkvh, bf16* __restrict__ qkvl,
    bf16* __restrict__ woh, bf16* __restrict__ wol,
    bf16* __restrict__ w1h, bf16* __restrict__ w1l,
    bf16* __restrict__ w2h, bf16* __restrict__ w2l)
{
    __shared__ float t[32][33];
    int b = blockIdx.x;
    const float* W; bf16 *Th, *Tl; int K, N;
    if (b < 4096) {
        int s = b >> 10; b &= 1023; K = 1024; N = 1024;
        if (s == 0)      { W = Wq; Th = qkvh; Tl = qkvl; }
        else if (s == 1) { W = Wk; Th = qkvh + (size_t)1024 * 1024;
                           Tl = qkvl + (size_t)1024 * 1024; }
        else if (s == 2) { W = Wv; Th = qkvh + (size_t)2048 * 1024;
                           Tl = qkvl + (size_t)2048 * 1024; }
        else             { W = Wo; Th = woh; Tl = wol; }
    } else if (b < 8192) {
        b -= 4096; W = W1; Th = w1h; Tl = w1l; K = 1024; N = 4096;
    } else {
        b -= 8192; W = W2; Th = w2h; Tl = w2l; K = 4096; N = 1024;
    }
    const int nb = N / 32;
    const int n0 = (b % nb) * 32, k0 = (b / nb) * 32;
    const int tx = threadIdx.x, ty = threadIdx.y;
    #pragma unroll
    for (int i = 0; i < 4; i++)
        t[ty + i * 8][tx] = W[(size_t)(k0 + ty + i * 8) * N + n0 + tx];
    __syncthreads();
    #pragma unroll
    for (int i = 0; i < 4; i++) {
        float v = t[tx][ty + i * 8];
        bf16 h, l; split_bf16(v, h, l);
        size_t o = (size_t)(n0 + ty + i * 8) * K + k0 + tx;
        Th[o] = h; Tl[o] = l;
    }
}

__global__ void bias_concat_kernel(const float* bq, const float* bk, const float* bv,
                                   float* out) {
    int i = blockIdx.x * 1024 + threadIdx.x;
    out[i] = (i < 1024) ? bq[i] : (i < 2048) ? bk[i - 1024] : bv[i - 2048];
}

// ---------------------------------------------------------------------------
// LayerNorm -> bf16 hi/lo split output
// ---------------------------------------------------------------------------
__device__ __forceinline__ float block_sum_256(float v, float* red) {
    __syncthreads();
    #pragma unroll
    for (int o = 16; o; o >>= 1) v += __shfl_xor_sync(0xffffffffu, v, o);
    if ((threadIdx.x & 31) == 0) red[threadIdx.x >> 5] = v;
    __syncthreads();
    if (threadIdx.x < 32) {
        float w = (threadIdx.x < 8) ? red[threadIdx.x] : 0.0f;
        #pragma unroll
        for (int o = 4; o; o >>= 1) w += __shfl_xor_sync(0xffffffffu, w, o);
        if (threadIdx.x == 0) red[0] = w;
    }
    __syncthreads();
    return red[0];
}

__global__ __launch_bounds__(256) void ln_split_kernel(
    const float* __restrict__ x, const float* __restrict__ g,
    const float* __restrict__ b, bf16* __restrict__ oh, bf16* __restrict__ ol)
{
    __shared__ float red[32];
    const int row = blockIdx.x;
    const int t = threadIdx.x;
    float4 v = reinterpret_cast<const float4*>(x + (size_t)row * D_MODEL)[t];

    float s = v.x + v.y + v.z + v.w;
    float mu = block_sum_256(s, red) * (1.0f / (float)D_MODEL);

    float dx = v.x - mu, dy = v.y - mu, dz = v.z - mu, dw = v.w - mu;
    float sq = dx * dx + dy * dy + dz * dz + dw * dw;
    float var = block_sum_256(sq, red) * (1.0f / (float)D_MODEL);
    float inv = rsqrtf(var + 1e-5f);

    float4 gg = reinterpret_cast<const float4*>(g)[t];
    float4 bb = reinterpret_cast<const float4*>(b)[t];
    float o0 = dx * inv * gg.x + bb.x;
    float o1 = dy * inv * gg.y + bb.y;
    float o2 = dz * inv * gg.z + bb.z;
    float o3 = dw * inv * gg.w + bb.w;

    bf16 h0, l0, h1, l1, h2, l2, h3, l3;
    split_bf16(o0, h0, l0); split_bf16(o1, h1, l1);
    split_bf16(o2, h2, l2); split_bf16(o3, h3, l3);
    size_t off = (size_t)row * D_MODEL + t * 4;
    __nv_bfloat162* ph = reinterpret_cast<__nv_bfloat162*>(oh + off);
    ph[0] = __halves2bfloat162(h0, h1);
    ph[1] = __halves2bfloat162(h2, h3);
    __nv_bfloat162* pl = reinterpret_cast<__nv_bfloat162*>(ol + off);
    pl[0] = __halves2bfloat162(l0, l1);
    pl[1] = __halves2bfloat162(l2, l3);
}

// ---------------------------------------------------------------------------
// Shared GEMM building blocks (SW128 swizzle, ldmatrix, mma)
// ---------------------------------------------------------------------------
__device__ __forceinline__ uint32_t swz_addr(uint32_t base, int r, int b) {
    return base + r * 128 + ((((b >> 4) ^ (r & 7)) & 7) << 4) + (b & 15);
}

// A-fragment 16x16 at (rows R..R+15, bytes cb..cb+31) via one ldmatrix.x4.
// d order: (R,cb),(R+8,cb),(R,cb+16),(R+8,cb+16).
__device__ __forceinline__ void ldsm_a(uint32_t d[4], uint32_t base, int lane,
                                       int R, int cb) {
    const int row = R + (lane & 7) + (((lane >> 3) & 1) << 3);
    const int byt = cb + ((lane >> 4) << 4);
    const uint32_t addr = swz_addr(base, row, byt);
    asm volatile("ldmatrix.sync.aligned.m8n8.x4.shared.b16 {%0,%1,%2,%3}, [%4];"
                 : "=r"(d[0]), "=r"(d[1]), "=r"(d[2]), "=r"(d[3]) : "r"(addr));
}

// B-fragments for two adjacent n8 tiles:
// d0=(N0,cb) d1=(N0,cb+16) d2=(N0+8,cb) d3=(N0+8,cb+16)
__device__ __forceinline__ void ldsm_b2(uint32_t d[4], uint32_t base, int lane,
                                        int N0, int cb) {
    const int row = N0 + (lane & 7) + ((lane >> 4) << 3);
    const int byt = cb + (((lane >> 3) & 1) << 4);
    const uint32_t addr = swz_addr(base, row, byt);
    asm volatile("ldmatrix.sync.aligned.m8n8.x4.shared.b16 {%0,%1,%2,%3}, [%4];"
                 : "=r"(d[0]), "=r"(d[1]), "=r"(d[2]), "=r"(d[3]) : "r"(addr));
}

__device__ __forceinline__ void mma_bf16(float c[4], const uint32_t a[4],
                                         const uint32_t b[2]) {
    asm volatile(
        "mma.sync.aligned.m16n8k16.row.col.f32.bf16.bf16.f32 "
        "{%0,%1,%2,%3}, {%4,%5,%6,%7}, {%8,%9}, {%0,%1,%2,%3};"
        : "+f"(c[0]), "+f"(c[1]), "+f"(c[2]), "+f"(c[3])
        : "r"(a[0]), "r"(a[1]), "r"(a[2]), "r"(a[3]), "r"(b[0]), "r"(b[1]));
}

// ---------------------------------------------------------------------------
// bf16 split-precision tensor-core GEMM (R12 schedule, unchanged).
// ---------------------------------------------------------------------------
#define BK 32
#define STAGE_BYTES 32768
#define A_HALF_BYTES 16384
#define STAGES 3
#define GEMM_SMEM_BYTES (STAGES * STAGE_BYTES)   // 98304

__global__ __launch_bounds__(256, 2) void gemm_bf16_kernel(
    const bf16* __restrict__ Ah, const bf16* __restrict__ Al,
    const bf16* __restrict__ Bh, const bf16* __restrict__ Bl,
    const float* __restrict__ bias, const float* __restrict__ resid,
    float* __restrict__ Cf, bf16* __restrict__ Ch, bf16* __restrict__ Cl,
    int M, int N, int K, int relu)
{
    extern __shared__ char smc[];
    const int tid = threadIdx.x;
    const int lane = tid & 31;
    const int w = tid >> 5;
    const int wm = w & 1, wn = w >> 1;
    const int g = lane >> 2, tg = lane & 3;
    const int bx = blockIdx.x, by = blockIdx.y;

    const bf16* Asrc[2] = {Ah + (size_t)(by * 128) * K, Al + (size_t)(by * 128) * K};
    const bf16* Bsrc[2] = {Bh + (size_t)(bx * 128) * K, Bl + (size_t)(bx * 128) * K};

    uint32_t smem_base = (uint32_t)__cvta_generic_to_shared(smc);

    float acc[4][4][4];
    #pragma unroll
    for (int mi = 0; mi < 4; mi++)
        #pragma unroll
        for (int ni = 0; ni < 4; ni++)
            #pragma unroll
            for (int c = 0; c < 4; c++) acc[mi][ni][c] = 0.0f;

    const int nk = K / BK;

#define LOAD_STAGE(s, k0)                                                     \
    do {                                                                      \
        uint32_t sb = smem_base + (s) * STAGE_BYTES;                          \
        _Pragma("unroll")                                                     \
        for (int i = 0; i < 4; i++) {                                         \
            int f = i * 256 + tid;                                            \
            int row = f >> 3, c = f & 7;                                      \
            uint32_t sw = ((uint32_t)((c ^ (row & 7)) & 7)) << 4;             \
            uint32_t dA = sb + row * 128 + sw;                                \
            uint32_t dB = dA + A_HALF_BYTES;                                  \
            const bf16* sA = Asrc[c >> 2] + (size_t)row * K + (k0) + (c & 3) * 8; \
            const bf16* sB = Bsrc[c >> 2] + (size_t)row * K + (k0) + (c & 3) * 8; \
            asm volatile("cp.async.cg.shared.global [%0], [%1], 16;" ::       \
                         "r"(dA), "l"(sA));                                   \
            asm volatile("cp.async.cg.shared.global [%0], [%1], 16;" ::       \
                         "r"(dB), "l"(sB));                                   \
        }                                                                     \
        asm volatile("cp.async.commit_group;");                               \
    } while (0)

    LOAD_STAGE(0, 0);
    LOAD_STAGE(1, BK);

    for (int kt = 0; kt < nk; kt++) {
        asm volatile("cp.async.wait_group 1;" ::: "memory");
        __syncthreads();

        const uint32_t sAu = smem_base + (kt % STAGES) * STAGE_BYTES;
        const uint32_t sBu = sAu + A_HALF_BYTES;

        #pragma unroll
        for (int kf = 0; kf < 2; kf++) {
            const int cb = kf * 32;
            uint32_t fAh[4][4], fBh[4][2], fAl[4][4], fBl[4][2];

            #pragma unroll
            for (int mi = 0; mi < 4; mi++)
                ldsm_a(fAh[mi], sAu, lane, wm * 64 + mi * 16, cb);
            #pragma unroll
            for (int np = 0; np < 2; np++) {
                uint32_t t4[4];
                ldsm_b2(t4, sBu, lane, wn * 32 + np * 16, cb);
                fBh[np * 2][0] = t4[0]; fBh[np * 2][1] = t4[1];
                fBh[np * 2 + 1][0] = t4[2]; fBh[np * 2 + 1][1] = t4[3];
            }
            #pragma unroll
            for (int mi = 0; mi < 4; mi++)
                ldsm_a(fAl[mi], sAu, lane, wm * 64 + mi * 16, cb + 64);

            if (kf == 0) {
                if (kt + 2 < nk) {
                    LOAD_STAGE((kt + 2) % STAGES, (kt + 2) * BK);
                } else {
                    asm volatile("cp.async.commit_group;");
                }
            }

            #pragma unroll
            for (int mi = 0; mi < 4; mi++)
                #pragma unroll
                for (int ni = 0; ni < 4; ni++)
                    mma_bf16(acc[mi][ni], fAh[mi], fBh[ni]);

            #pragma unroll
            for (int np = 0; np < 2; np++) {
                uint32_t t4[4];
                ldsm_b2(t4, sBu, lane, wn * 32 + np * 16, cb + 64);
                fBl[np * 2][0] = t4[0]; fBl[np * 2][1] = t4[1];
                fBl[np * 2 + 1][0] = t4[2]; fBl[np * 2 + 1][1] = t4[3];
            }

            #pragma unroll
            for (int mi = 0; mi < 4; mi++)
                #pragma unroll
                for (int ni = 0; ni < 4; ni++)
                    mma_bf16(acc[mi][ni], fAl[mi], fBh[ni]);

            #pragma unroll
            for (int mi = 0; mi < 4; mi++)
                #pragma unroll
                for (int ni = 0; ni < 4; ni++)
                    mma_bf16(acc[mi][ni], fAh[mi], fBl[ni]);
        }
    }

    const int bm = by * 128 + wm * 64;
    const int bn = bx * 128 + wn * 32;
    #pragma unroll
    for (int mi = 0; mi < 4; mi++) {
        #pragma unroll
        for (int ni = 0; ni < 4; ni++) {
            const int c0 = bn + ni * 8 + tg * 2;
            const float b0 = bias[c0], b1 = bias[c0 + 1];
            #pragma unroll
            for (int half = 0; half < 2; half++) {
                const int r = bm + mi * 16 + g + half * 8;
                float v0 = acc[mi][ni][half * 2 + 0] + b0;
                float v1 = acc[mi][ni][half * 2 + 1] + b1;
                if (resid) {
                    const float2 rr = *reinterpret_cast<const float2*>(
                        resid + (size_t)r * N + c0);
                    v0 += rr.x; v1 += rr.y;
                }
                if (relu) { v0 = fmaxf(v0, 0.0f); v1 = fmaxf(v1, 0.0f); }
                if (Cf) {
                    float2 o; o.x = v0; o.y = v1;
                    *reinterpret_cast<float2*>(Cf + (size_t)r * N + c0) = o;
                }
                if (Ch) {
                    bf16 h0, l0, h1, l1;
                    split_bf16(v0, h0, l0); split_bf16(v1, h1, l1);
                    *reinterpret_cast<__nv_bfloat162*>(Ch + (size_t)r * N + c0) =
                        __halves2bfloat162(h0, h1);
                    *reinterpret_cast<__nv_bfloat162*>(Cl + (size_t)r * N + c0) =
                        __halves2bfloat162(l0, l1);
                }
            }
        }
    }
}

// ---------------------------------------------------------------------------
// Causal flash attention, FA2-style register-resident P (R13/R14).
// 256 threads = 8 warps; warp w owns q rows [w*16, w*16+16), ALL 128 j.
// QK C-fragments ARE the PV A-fragments (k=j): P never touches smem.
// Softmax per-row entirely within one warp (shfl over tg). 2 barriers/tile.
// Smem = Q(32KB) + K(32KB) + Vt(32KB) = 96KB -> 2 CTAs/SM.
// Longest-first scheduling: qt = gridDim.x-1-blockIdx.x.
// ---------------------------------------------------------------------------
#define AT_Q_OFF   0
#define AT_K_OFF   32768
#define AT_VT_OFF  65536
#define ATTN_SMEM_BYTES 98304

#define SWZ(r, b) (((((b) >> 4) ^ ((r) & 7)) & 7) << 4 | ((b) & 15))

__global__ __launch_bounds__(256, 2) void attn_mma_kernel(
    const bf16* __restrict__ QKVh, const bf16* __restrict__ QKVl,
    bf16* __restrict__ Oh, bf16* __restrict__ Ol)
{
    extern __shared__ char smc[];
    const int qt = (int)gridDim.x - 1 - (int)blockIdx.x;   // longest first
    const int hh = blockIdx.y, bb = blockIdx.z;
    const int tid = threadIdx.x;
    const int lane = tid & 31;
    const int w = tid >> 5;
    const int g = lane >> 2, tg = lane & 3;
    const int qbase = qt * 128;
    const int grow0 = bb * S_LEN + qbase;
    uint32_t smem_base = (uint32_t)__cvta_generic_to_shared(smc);

#define AT_LOAD_TILE(dstoff, rbase, colbase)                                  \
    do {                                                                      \
        _Pragma("unroll")                                                     \
        for (int i = 0; i < 4; i++) {                                         \
            int f = i * 256 + tid;                                            \
            int row = f >> 3, c = f & 7;                                      \
            uint32_t dst = smem_base + (dstoff) + row * 128 +                 \
                           (((uint32_t)((c ^ (row & 7)) & 7)) << 4);          \
            const bf16* src = ((c < 4) ? QKVh : QKVl) +                       \
                (size_t)((rbase) + row) * QKV_N + (colbase) + (c & 3) * 8;    \
            asm volatile("cp.async.cg.shared.global [%0], [%1], 16;" ::       \
                         "r"(dst), "l"(src));                                 \
        }                                                                     \
    } while (0)

    // Q tiles (2 chunks)
    AT_LOAD_TILE(AT_Q_OFF, grow0, hh * 64);
    AT_LOAD_TILE(AT_Q_OFF + 16384, grow0, hh * 64 + 32);
    asm volatile("cp.async.commit_group;");

    float m0 = -INFINITY, m1 = -INFINITY, l0 = 0.0f, l1 = 0.0f;
    float oacc[8][4];
    #pragma unroll
    for (int ct = 0; ct < 8; ct++)
        #pragma unroll
        for (int c = 0; c < 4; c++) oacc[ct][c] = 0.0f;

    for (int kt = 0; kt <= qt; kt++) {
        const int kbase = kt * 128;
        const int krow0 = bb * S_LEN + kbase;

        AT_LOAD_TILE(AT_K_OFF, krow0, 1024 + hh * 64);
        AT_LOAD_TILE(AT_K_OFF + 16384, krow0, 1024 + hh * 64 + 32);
        asm volatile("cp.async.commit_group;");

        // V transpose: V[j][c] -> Vt[c][j] hi/lo (B-layout, 4 j-chunks)
        {
            const int cg = (tid & 15) * 4;
            const int j0 = tid >> 4;
            #pragma unroll
            for (int jj = 0; jj < 8; jj++) {
                const int j = j0 + jj * 16;
                const size_t goff = (size_t)(krow0 + j) * QKV_N + 2048 +
                                    hh * 64 + cg;
                unsigned long long vh =
                    *reinterpret_cast<const unsigned long long*>(QKVh + goff);
                unsigned long long vl =
                    *reinterpret_cast<const unsigned long long*>(QKVl + goff);
                const int cbase = AT_VT_OFF + (j >> 5) * 8192;
                const int bh = (j & 31) * 2;
                #pragma unroll
                for (int u = 0; u < 4; u++) {
                    const int c = cg + u;
                    unsigned short eh = (unsigned short)(vh >> (16 * u));
                    unsigned short el = (unsigned short)(vl >> (16 * u));
                    *reinterpret_cast<unsigned short*>(
                        smc + cbase + c * 128 + SWZ(c, bh)) = eh;
                    *reinterpret_cast<unsigned short*>(
                        smc + cbase + c * 128 + SWZ(c, bh + 64)) = el;
                }
            }
        }

        asm volatile("cp.async.wait_group 0;" ::: "memory");
        __syncthreads();   // (1) Q, K, Vt ready; prev-tile consumers done

        // ---- QK^T: warp computes 16 q-rows x 128 j ----
        float acc[16][4];
        #pragma unroll
        for (int nt = 0; nt < 16; nt++)
            #pragma unroll
            for (int c = 0; c < 4; c++) acc[nt][c] = 0.0f;

        #pragma unroll
        for (int ck = 0; ck < 2; ck++) {
            const uint32_t sQ = smem_base + AT_Q_OFF + ck * 16384;
            const uint32_t sK = smem_base + AT_K_OFF + ck * 16384;
            #pragma unroll
            for (int kf = 0; kf < 2; kf++) {
                const int cb = kf * 32;
                uint32_t fAh[4], fAl[4];
                ldsm_a(fAh, sQ, lane, w * 16, cb);
                ldsm_a(fAl, sQ, lane, w * 16, cb + 64);
                #pragma unroll
                for (int nt2 = 0; nt2 < 8; nt2++) {
                    uint32_t th[4], tl[4];
                    ldsm_b2(th, sK, lane, nt2 * 16, cb);
                    uint32_t bh0[2] = {th[0], th[1]};
                    uint32_t bh1[2] = {th[2], th[3]};
                    mma_bf16(acc[nt2 * 2], fAh, bh0);
                    mma_bf16(acc[nt2 * 2 + 1], fAh, bh1);
                    mma_bf16(acc[nt2 * 2], fAl, bh0);
                    mma_bf16(acc[nt2 * 2 + 1], fAl, bh1);
                    ldsm_b2(tl, sK, lane, nt2 * 16, cb + 64);
                    uint32_t bl0[2] = {tl[0], tl[1]};
                    uint32_t bl1[2] = {tl[2], tl[3]};
                    mma_bf16(acc[nt2 * 2], fAh, bl0);
                    mma_bf16(acc[nt2 * 2 + 1], fAh, bl1);
                }
            }
        }

        // ---- scale + causal mask (rows r0 = w*16+g, r1 = r0+8) ----
        const int qi0 = qbase + w * 16 + g;
        const int qi1 = qi0 + 8;
        #pragma unroll
        for (int nt = 0; nt < 16; nt++) {
            const int kj = kbase + nt * 8 + tg * 2;
            acc[nt][0] = (kj     <= qi0) ? acc[nt][0] * 0.125f : -1e30f;
            acc[nt][1] = (kj + 1 <= qi0) ? acc[nt][1] * 0.125f : -1e30f;
            acc[nt][2] = (kj     <= qi1) ? acc[nt][2] * 0.125f : -1e30f;
            acc[nt][3] = (kj + 1 <= qi1) ? acc[nt][3] * 0.125f : -1e30f;
        }

        // ---- row max (shfl over tg only) ----
        float t0 = -INFINITY, t1 = -INFINITY;
        #pragma unroll
        for (int nt = 0; nt < 16; nt++) {
            t0 = fmaxf(t0, fmaxf(acc[nt][0], acc[nt][1]));
            t1 = fmaxf(t1, fmaxf(acc[nt][2], acc[nt][3]));
        }
        t0 = fmaxf(t0, __shfl_xor_sync(0xffffffffu, t0, 1));
        t0 = fmaxf(t0, __shfl_xor_sync(0xffffffffu, t0, 2));
        t1 = fmaxf(t1, __shfl_xor_sync(0xffffffffu, t1, 1));
        t1 = fmaxf(t1, __shfl_xor_sync(0xffffffffu, t1, 2));
        const float nm0 = fmaxf(m0, t0);
        const float nm1 = fmaxf(m1, t1);
        const float sc0 = fast_exp(m0 - nm0);
        const float sc1 = fast_exp(m1 - nm1);
        m0 = nm0; m1 = nm1;

        // ---- exp + row sums + in-register P hi/lo pack ----
        float s0 = 0.0f, s1 = 0.0f;
        uint32_t aPh[8][4], aPl[8][4];
        #pragma unroll
        for (int t = 0; t < 8; t++) {
            float p00 = fast_exp(acc[2 * t][0] - nm0);
            float p01 = fast_exp(acc[2 * t][1] - nm0);
            float p02 = fast_exp(acc[2 * t][2] - nm1);
            float p03 = fast_exp(acc[2 * t][3] - nm1);
            float p10 = fast_exp(acc[2 * t + 1][0] - nm0);
            float p11 = fast_exp(acc[2 * t + 1][1] - nm0);
            float p12 = fast_exp(acc[2 * t + 1][2] - nm1);
            float p13 = fast_exp(acc[2 * t + 1][3] - nm1);
            s0 += p00 + p01 + p10 + p11;
            s1 += p02 + p03 + p12 + p13;
            bf16 h0, lo0, h1, lo1;
            split_bf16(p00, h0, lo0); split_bf16(p01, h1, lo1);
            aPh[t][0] = pack2(h0, h1);
            aPl[t][0] = pack2(lo0, lo1);
            split_bf16(p02, h0, lo0); split_bf16(p03, h1, lo1);
            aPh[t][1] = pack2(h0, h1);
            aPl[t][1] = pack2(lo0, lo1);
            split_bf16(p10, h0, lo0); split_bf16(p11, h1, lo1);
            aPh[t][2] = pack2(h0, h1);
            aPl[t][2] = pack2(lo0, lo1);
            split_bf16(p12, h0, lo0); split_bf16(p13, h1, lo1);
            aPh[t][3] = pack2(h0, h1);
            aPl[t][3] = pack2(lo0, lo1);
        }
        s0 += __shfl_xor_sync(0xffffffffu, s0, 1);
        s0 += __shfl_xor_sync(0xffffffffu, s0, 2);
        s1 += __shfl_xor_sync(0xffffffffu, s1, 1);
        s1 += __shfl_xor_sync(0xffffffffu, s1, 2);
        l0 = l0 * sc0 + s0;
        l1 = l1 * sc1 + s1;

        // ---- rescale O, then PV (P from registers, V from smem) ----
        #pragma unroll
        for (int ct = 0; ct < 8; ct++) {
            oacc[ct][0] *= sc0; oacc[ct][1] *= sc0;
            oacc[ct][2] *= sc1; oacc[ct][3] *= sc1;
        }
        #pragma unroll
        for (int cj = 0; cj < 4; cj++) {
            const uint32_t sV = smem_base + AT_VT_OFF + cj * 8192;
            #pragma unroll
            for (int kf2 = 0; kf2 < 2; kf2++) {
                const int t = cj * 2 + kf2;
                const int cb = kf2 * 32;
                #pragma unroll
                for (int ct2 = 0; ct2 < 4; ct2++) {
                    uint32_t vh[4], vl[4];
                    ldsm_b2(vh, sV, lane, ct2 * 16, cb);
                    uint32_t bh0[2] = {vh[0], vh[1]};
                    uint32_t bh1[2] = {vh[2], vh[3]};
                    mma_bf16(oacc[ct2 * 2], aPh[t], bh0);
                    mma_bf16(oacc[ct2 * 2 + 1], aPh[t], bh1);
                    mma_bf16(oacc[ct2 * 2], aPl[t], bh0);
                    mma_bf16(oacc[ct2 * 2 + 1], aPl[t], bh1);
                    ldsm_b2(vl, sV, lane, ct2 * 16, cb + 64);
                    uint32_t bl0[2] = {vl[0], vl[1]};
                    uint32_t bl1[2] = {vl[2], vl[3]};
                    mma_bf16(oacc[ct2 * 2], aPh[t], bl0);
                    mma_bf16(oacc[ct2 * 2 + 1], aPh[t], bl1);
                }
            }
        }
        __syncthreads();   // (2) K/Vt reusable next tile
    }

    // ---- output: rows w*16+g (+8), cols hh*64 + ct*8 + tg*2 ----
    const float inv0 = 1.0f / l0;
    const float inv1 = 1.0f / l1;
    const size_t row0 = (size_t)(grow0 + w * 16 + g) * D_MODEL;
    const size_t row1 = (size_t)(grow0 + w * 16 + g + 8) * D_MODEL;
    #pragma unroll
    for (int ct = 0; ct < 8; ct++) {
        const int col = hh * 64 + ct * 8 + tg * 2;
        bf16 h0, lo0, h1, lo1;
        split_bf16(oacc[ct][0] * inv0, h0, lo0);
        split_bf16(oacc[ct][1] * inv0, h1, lo1);
        *reinterpret_cast<__nv_bfloat162*>(Oh + row0 + col) =
            __halves2bfloat162(h0, h1);
        *reinterpret_cast<__nv_bfloat162*>(Ol + row0 + col) =
            __halves2bfloat162(lo0, lo1);
        split_bf16(oacc[ct][2] * inv1, h0, lo0);
        split_bf16(oacc[ct][3] * inv1, h1, lo1);
        *reinterpret_cast<__nv_bfloat162*>(Oh + row1 + col) =
            __halves2bfloat162(h0, h1);
        *reinterpret_cast<__nv_bfloat162*>(Ol + row1 + col) =
            __halves2bfloat162(lo0, lo1);
    }
}

// ---------------------------------------------------------------------------
// kernel_launch
// ---------------------------------------------------------------------------
extern "C" void kernel_launch(void* const* d_in, const int* in_sizes, int n_in,
                              void* d_out, int out_size)
{
    const float* x   = (const float*)d_in[0];
    const float* Wq  = (const float*)d_in[2];
    const float* bq  = (const float*)d_in[3];
    const float* Wk  = (const float*)d_in[4];
    const float* bk  = (const float*)d_in[5];
    const float* Wv  = (const float*)d_in[6];
    const float* bv  = (const float*)d_in[7];
    const float* Wo  = (const float*)d_in[8];
    const float* bo  = (const float*)d_in[9];
    const float* W1  = (const float*)d_in[10];
    const float* b1  = (const float*)d_in[11];
    const float* W2  = (const float*)d_in[12];
    const float* b2  = (const float*)d_in[13];
    const float* g1  = (const float*)d_in[14];
    const float* be1 = (const float*)d_in[15];
    const float* g2  = (const float*)d_in[16];
    const float* be2 = (const float*)d_in[17];
    float* out = (float*)d_out;

    bf16 *xnh, *xnl, *qkvh, *qkvl, *ath, *atl, *hnh, *hnl, *ffh, *ffl;
    bf16 *wqkvh, *wqkvl, *woh, *wol, *w1h, *w1l, *w2h, *w2l;
    float *h, *bqkv;
    cudaGetSymbolAddress((void**)&xnh, g_xn_h);
    cudaGetSymbolAddress((void**)&xnl, g_xn_l);
    cudaGetSymbolAddress((void**)&qkvh, g_qkv_h);
    cudaGetSymbolAddress((void**)&qkvl, g_qkv_l);
    cudaGetSymbolAddress((void**)&ath, g_at_h);
    cudaGetSymbolAddress((void**)&atl, g_at_l);
    cudaGetSymbolAddress((void**)&h,   g_h);
    cudaGetSymbolAddress((void**)&hnh, g_hn_h);
    cudaGetSymbolAddress((void**)&hnl, g_hn_l);
    cudaGetSymbolAddress((void**)&ffh, g_ff_h);
    cudaGetSymbolAddress((void**)&ffl, g_ff_l);
    cudaGetSymbolAddress((void**)&wqkvh, g_wqkvT_h);
    cudaGetSymbolAddress((void**)&wqkvl, g_wqkvT_l);
    cudaGetSymbolAddress((void**)&woh, g_woT_h);
    cudaGetSymbolAddress((void**)&wol, g_woT_l);
    cudaGetSymbolAddress((void**)&w1h, g_w1T_h);
    cudaGetSymbolAddress((void**)&w1l, g_w1T_l);
    cudaGetSymbolAddress((void**)&w2h, g_w2T_h);
    cudaGetSymbolAddress((void**)&w2l, g_w2T_l);
    cudaGetSymbolAddress((void**)&bqkv, g_bqkv);

    cudaFuncSetAttribute(attn_mma_kernel, cudaFuncAttributeMaxDynamicSharedMemorySize,
                         ATTN_SMEM_BYTES);
    cudaFuncSetAttribute(gemm_bf16_kernel, cudaFuncAttributeMaxDynamicSharedMemorySize,
                         GEMM_SMEM_BYTES);

    const dim3 blk(256);
    const dim3 wblk(32, 8);

    // 1
    wconv_all_kernel<<<12288, wblk>>>(Wq, Wk, Wv, Wo, W1, W2,
                                      wqkvh, wqkvl, woh, wol,
                                      w1h, w1l, w2h, w2l);
    // 2
    bias_concat_kernel<<<3, 1024>>>(bq, bk, bv, bqkv);
    // 3
    ln_split_kernel<<<MROWS, blk>>>(x, g1, be1, xnh, xnl);
    // 4: QKV projection -> bf16 hi/lo
    gemm_bf16_kernel<<<dim3(QKV_N / 128, MROWS / 128), blk, GEMM_SMEM_BYTES>>>(
        xnh, xnl, wqkvh, wqkvl, bqkv, nullptr, nullptr, qkvh, qkvl,
        MROWS, QKV_N, D_MODEL, 0);
    // 5: tensor-core attention
    attn_mma_kernel<<<dim3(S_LEN / 128, NH, BATCH), blk, ATTN_SMEM_BYTES>>>(
        qkvh, qkvl, ath, atl);
    // 6 (profiled)
    gemm_bf16_kernel<<<dim3(D_MODEL / 128, MROWS / 128), blk, GEMM_SMEM_BYTES>>>(
        ath, atl, woh, wol, bo, x, h, nullptr, nullptr,
        MROWS, D_MODEL, D_MODEL, 0);
    // 7
    ln_split_kernel<<<MROWS, blk>>>(h, g2, be2, hnh, hnl);
    // 8
    gemm_bf16_kernel<<<dim3(DFF / 128, MROWS / 128), blk, GEMM_SMEM_BYTES>>>(
        hnh, hnl, w1h, w1l, b1, nullptr, nullptr, ffh, ffl,
        MROWS, DFF, D_MODEL, 1);
    // 9
    gemm_bf16_kernel<<<dim3(D_MODEL / 128, MROWS / 128), blk, GEMM_SMEM_BYTES>>>(
        ffh, ffl, w2h, w2l, b2, h, out, nullptr, nullptr,
        MROWS, D_MODEL, DFF, 0);
}